// round 13
// baseline (speedup 1.0000x reference)
#include <cuda_runtime.h>
#include <cstdint>
#include <cstddef>

#define NB 32
#define DD 128
#define NN 4096
#define NC 64
#define DR 25

// output layout: logits | cam | bag | x
#define OUT_CAM  ((size_t)2048)
#define OUT_BAG  ((size_t)8390656)   // 2048 + 32*64*4096
#define OUT_X    ((size_t)8394752)   // + 32*128

__device__ float g_peT[DD * NN];     // 2 MB transposed pe
__device__ float g_bag[NB * DD];

static __device__ __forceinline__ unsigned long long ffma2(unsigned long long a,
                                                           unsigned long long b,
                                                           unsigned long long c) {
    unsigned long long d;
    asm("fma.rn.f32x2 %0, %1, %2, %3;" : "=l"(d) : "l"(a), "l"(b), "l"(c));
    return d;
}
static __device__ __forceinline__ unsigned long long dup2(float f) {
    unsigned long long d;
    asm("mov.b64 %0, {%1, %1};" : "=l"(d) : "f"(f));
    return d;
}
static __device__ __forceinline__ unsigned long long pack2(float a, float b) {
    unsigned long long d;
    asm("mov.b64 %0, {%1, %2};" : "=l"(d) : "f"(a), "f"(b));
    return d;
}
static __device__ __forceinline__ float2 unpack2(unsigned long long v) {
    float2 r;
    asm("mov.b64 {%0, %1}, %2;" : "=f"(r.x), "=f"(r.y) : "l"(v));
    return r;
}

// ---------------- pe transpose: g_peT[d][n] = pe[n][d] ----------------
__global__ void k_transpose(const float* __restrict__ pe) {
    __shared__ float t[32][33];
    int n0 = blockIdx.x * 32, d0 = blockIdx.y * 32;
    int tx = threadIdx.x, ty = threadIdx.y;  // 32 x 8
#pragma unroll
    for (int j = 0; j < 32; j += 8)
        t[ty + j][tx] = pe[(size_t)(n0 + ty + j) * DD + d0 + tx];
    __syncthreads();
#pragma unroll
    for (int j = 0; j < 32; j += 8)
        g_peT[(size_t)(d0 + ty + j) * NN + n0 + tx] = t[tx][ty + j];
}

// partial rank-mask for i in [I0, I1): bit rank(i) set. Stable ties (j<i).
template <int I0, int I1>
static __device__ __forceinline__ unsigned long long maskpart(const float (&s)[NC]) {
    unsigned long long pm = 0ull;
#pragma unroll
    for (int i = I0; i < I1; ++i) {
        int r = 0;
#pragma unroll
        for (int j = 0; j < NC; ++j) r += (s[j] > s[i]) ? 1 : 0;
#pragma unroll
        for (int j = 0; j < i; ++j) r += (s[j] == s[i]) ? 1 : 0;
        pm |= (1ull << r);
    }
    return pm;
}

// ---------------- main: e = fl(x+pe) joint, strictly sequential fp32 FMA over
//   d=0..127 per class (Eigen gebp order). Warp-split: warps 0-1 = classes
//   0-31 (+x copy), warps 2-3 = classes 32-63; each thread owns 2 columns.
//   W broadcast LDS halved; mask work split across halves via smem. ----------
__global__ void __launch_bounds__(128) k_main(const float* __restrict__ x,
                                              const float* __restrict__ W,
                                              float* __restrict__ out) {
    // W2s[d][cp] = ( W[2cp][d], W[2cp+1][d] ), 32KB. Reused as sex2 after GEMM.
    __shared__ __align__(16) unsigned long long W2s[DD * 32];
    __shared__ unsigned long long pmask[2][128];
    int tid = threadIdx.x;
    int lane = tid & 31, wid = tid >> 5;
    int h = wid >> 1;            // class-half: 0 -> classes 0-31, 1 -> 32-63
    int cg = wid & 1;            // column group: 0 -> cols 0-63, 1 -> 64-127
    int b = blockIdx.y;
    int colA = cg * 64 + lane;   // local columns
    int colB = colA + 32;
    int nA = blockIdx.x * 128 + colA;
    int nB = nA + 32;

    for (int idx = tid; idx < DD * 32; idx += 128) {
        int d = idx >> 5, cp = idx & 31;
        W2s[idx] = pack2(W[(2 * cp) * DD + d], W[(2 * cp + 1) * DD + d]);
    }
    __syncthreads();

    const float* xb = x + (size_t)b * DD * NN;
    float* xcopy = out + OUT_X + (size_t)b * DD * NN;

    unsigned long long accA[16], accB[16];
#pragma unroll
    for (int p = 0; p < 16; ++p) { accA[p] = 0ull; accB[p] = 0ull; }

#pragma unroll 4
    for (int d = 0; d < DD; ++d) {
        float xa = xb[(size_t)d * NN + nA];
        float xv = xb[(size_t)d * NN + nB];
        if (h == 0) {                          // warp-uniform branch
            xcopy[(size_t)d * NN + nA] = xa;
            xcopy[(size_t)d * NN + nB] = xv;
        }
        float eA = xa + g_peT[(size_t)d * NN + nA];   // fl(x+pe), matches ref
        float eB = xv + g_peT[(size_t)d * NN + nB];
        unsigned long long e2A = dup2(eA), e2B = dup2(eB);
        const ulonglong2* wrow = (const ulonglong2*)&W2s[d * 32 + h * 16];
#pragma unroll
        for (int q = 0; q < 8; ++q) {
            ulonglong2 w = wrow[q];
            accA[2 * q]     = ffma2(w.x, e2A, accA[2 * q]);
            accB[2 * q]     = ffma2(w.x, e2B, accB[2 * q]);
            accA[2 * q + 1] = ffma2(w.y, e2A, accA[2 * q + 1]);
            accB[2 * q + 1] = ffma2(w.y, e2B, accB[2 * q + 1]);
        }
    }

    // exchange: sex2[classpair P][col] = u64 of (s[2P], s[2P+1]); reuse W2s.
    __syncthreads();                 // all warps done reading W2s
    unsigned long long* sex2 = W2s;
#pragma unroll
    for (int p = 0; p < 16; ++p) {
        sex2[(h * 16 + p) * 128 + colA] = accA[p];
        sex2[(h * 16 + p) * 128 + colB] = accB[p];
    }
    __syncthreads();

    // partial masks: half0 handles i=0..12, half1 handles i=13..24
    {
        float s[NC];
#pragma unroll
        for (int P = 0; P < 32; ++P) {
            float2 v = unpack2(sex2[P * 128 + colA]);
            s[2 * P] = v.x; s[2 * P + 1] = v.y;
        }
        pmask[h][colA] = (h == 0) ? maskpart<0, 13>(s) : maskpart<13, DR>(s);
    }
    {
        float s[NC];
#pragma unroll
        for (int P = 0; P < 32; ++P) {
            float2 v = unpack2(sex2[P * 128 + colB]);
            s[2 * P] = v.x; s[2 * P + 1] = v.y;
        }
        pmask[h][colB] = (h == 0) ? maskpart<0, 13>(s) : maskpart<13, DR>(s);
    }
    __syncthreads();

    // write cam: half h writes slots h*32..h*32+31 for its 2 columns
    float* camOut = out + OUT_CAM + (size_t)b * NC * NN;
    {
        unsigned long long m = pmask[0][colA] | pmask[1][colA];
        float sh[32];
#pragma unroll
        for (int p = 0; p < 16; ++p) {
            float2 v = unpack2(sex2[(h * 16 + p) * 128 + colA]);
            sh[2 * p] = v.x; sh[2 * p + 1] = v.y;
        }
#pragma unroll
        for (int k = 0; k < 32; ++k) {
            int r = h * 32 + k;
            camOut[(size_t)r * NN + nA] = ((m >> r) & 1ull) ? sh[k] : 0.0f;
        }
    }
    {
        unsigned long long m = pmask[0][colB] | pmask[1][colB];
        float sh[32];
#pragma unroll
        for (int p = 0; p < 16; ++p) {
            float2 v = unpack2(sex2[(h * 16 + p) * 128 + colB]);
            sh[2 * p] = v.x; sh[2 * p + 1] = v.y;
        }
#pragma unroll
        for (int k = 0; k < 32; ++k) {
            int r = h * 32 + k;
            camOut[(size_t)r * NN + nB] = ((m >> r) & 1ull) ? sh[k] : 0.0f;
        }
    }
}

// ---------------- bag: exact top-25 mean per (b,d) row ----------------
__global__ void __launch_bounds__(256) k_bag(const float* __restrict__ x,
                                             float* __restrict__ out) {
    __shared__ unsigned cand[NN];
    __shared__ unsigned s_T0;
    __shared__ int s_nc;
    __shared__ unsigned s_K;
    __shared__ float wsum[8];
    __shared__ int wcnt[8];

    int row = blockIdx.x;            // row = b*128 + d
    int d = row & 127;
    int tid = threadIdx.x;
    int lane = tid & 31, wid = tid >> 5;
    const float* xr = x + (size_t)row * NN;
    const float* pr = g_peT + (size_t)d * NN;

    if (tid == 0) { s_T0 = 0u; s_nc = 0; }

    unsigned key[16];
#pragma unroll
    for (int k = 0; k < 16; ++k) {
        int n = tid + (k << 8);
        float e = xr[n] + pr[n];
        unsigned u = __float_as_uint(e);
        key[k] = (u & 0x80000000u) ? ~u : (u | 0x80000000u);
    }

    unsigned h[8];
#pragma unroll
    for (int j = 0; j < 8; ++j)
        h[j] = (key[2 * j] >> 16) | (key[2 * j + 1] & 0xFFFF0000u);

    unsigned Kw = 0u;
#pragma unroll
    for (int bit = 15; bit >= 0; --bit) {
        unsigned test = Kw | (1u << bit);
        unsigned tp = test | (test << 16);
        unsigned c2 = 0u;
#pragma unroll
        for (int j = 0; j < 8; ++j) c2 += __vsetgeu2(h[j], tp);
        int c = (int)((c2 & 0xFFFFu) + (c2 >> 16));
        c = __reduce_add_sync(0xFFFFFFFFu, c);
        if (c >= DR) Kw = test;
    }

    __syncthreads();
    if (lane == 0) atomicMax(&s_T0, Kw);
    __syncthreads();
    unsigned T0 = s_T0;

#pragma unroll
    for (int k = 0; k < 16; ++k) {
        if ((key[k] >> 16) >= T0) {
            int p = atomicAdd(&s_nc, 1);
            cand[p] = key[k];
        }
    }
    __syncthreads();

    if (wid == 0) {
        int m = s_nc;
        unsigned K = 0u;
        for (int bit = 31; bit >= 0; --bit) {
            unsigned test = K | (1u << bit);
            int c = 0;
            for (int i = lane; i < m; i += 32)
                c += (cand[i] >= test) ? 1 : 0;
            c = __reduce_add_sync(0xFFFFFFFFu, c);
            if (c >= DR) K = test;
        }
        if (lane == 0) s_K = K;
    }
    __syncthreads();
    unsigned K = s_K;

    int cg = 0;
    float sm = 0.f;
#pragma unroll
    for (int k = 0; k < 16; ++k) {
        if (key[k] > K) {
            cg++;
            unsigned u = (key[k] & 0x80000000u) ? (key[k] ^ 0x80000000u) : ~key[k];
            sm += __uint_as_float(u);
        }
    }
#pragma unroll
    for (int off = 16; off > 0; off >>= 1) {
        cg += __shfl_down_sync(0xFFFFFFFFu, cg, off);
        sm += __shfl_down_sync(0xFFFFFFFFu, sm, off);
    }
    if (lane == 0) { wcnt[wid] = cg; wsum[wid] = sm; }
    __syncthreads();
    if (tid == 0) {
        int cgt = wcnt[0] + wcnt[1] + wcnt[2] + wcnt[3] + wcnt[4] + wcnt[5] + wcnt[6] + wcnt[7];
        float smt = wsum[0] + wsum[1] + wsum[2] + wsum[3] + wsum[4] + wsum[5] + wsum[6] + wsum[7];
        unsigned kk = (K & 0x80000000u) ? (K ^ 0x80000000u) : ~K;
        float kv = __uint_as_float(kk);
        float bag = (smt + (float)(DR - cgt) * kv) * (1.0f / 25.0f);
        g_bag[row] = bag;
        out[OUT_BAG + row] = bag;
    }
}

// ---------------- logits = bag @ W^T + b  (warp per 8 c's, float4 + shfl) ----
__global__ void __launch_bounds__(256) k_logits(const float* __restrict__ W,
                                                const float* __restrict__ bias,
                                                float* __restrict__ out) {
    int b = blockIdx.x;
    int lane = threadIdx.x & 31, wid = threadIdx.x >> 5;   // 8 warps
    float4 g = ((const float4*)(g_bag + b * DD))[lane];
#pragma unroll
    for (int i = 0; i < 8; ++i) {
        int c = wid * 8 + i;
        float4 w = __ldg((const float4*)(W + c * DD) + lane);
        float p = g.x * w.x + g.y * w.y + g.z * w.z + g.w * w.w;
#pragma unroll
        for (int off = 16; off > 0; off >>= 1)
            p += __shfl_down_sync(0xFFFFFFFFu, p, off);
        if (lane == 0) out[(size_t)b * NC + c] = p + bias[c];
    }
}

extern "C" void kernel_launch(void* const* d_in, const int* in_sizes, int n_in,
                              void* d_out, int out_size) {
    const float* x    = (const float*)d_in[0];
    const float* W    = (const float*)d_in[1];
    const float* bias = (const float*)d_in[2];
    const float* pe   = (const float*)d_in[3];
    float* out = (float*)d_out;

    k_transpose<<<dim3(128, 4), dim3(32, 8)>>>(pe);
    k_bag<<<4096, 256>>>(x, out);
    k_logits<<<32, 256>>>(W, bias, out);
    k_main<<<dim3(32, 32), 128>>>(x, W, out);
}